// round 11
// baseline (speedup 1.0000x reference)
#include <cuda_runtime.h>
#include <cuda_fp16.h>
#include <math.h>

#define N_MAX   100000
#define E_MAX   3200000
#define G_MAX   256
#define F3      30
#define NCLS    10

#define FIXSCALE 1048576.0f     // 2^20 fixed point for |w| degree accumulation
#define SCAN_BN  1024
#define SCAN_MAXB 128

// ---------------------------------------------------------------------------
// Device scratch (zero at module load; self-resetting across graph replays)
// ---------------------------------------------------------------------------
__device__ int                g_is64;
__device__ int                g_bat[N_MAX];
__device__ float              g_dis[N_MAX];     // D^{-1/2}
__device__ unsigned long long g_hd[N_MAX];      // (count<<32)|fixed_deg; zeroed on consume
__device__ int                g_rowptr[N_MAX + 1];
__device__ int                g_wofs[N_MAX];
__device__ int                g_bsum[SCAN_MAXB];
__device__ int                g_boff[SCAN_MAXB];
__device__ int2               g_csr[E_MAX];     // {src, half2(|w|,|w|)}
__device__ __half             g_xw[N_MAX * 96]; // layer-1 xw' (also reused for xw3')
__device__ __half             g_xw2[N_MAX * 96];
__device__ float              g_pool[G_MAX * F3];   // zeroed by final after use
__device__ float              g_cnt[G_MAX];

// ---------------------------------------------------------------------------
// Side stream + events (static init, before harness memory checkpoints)
// ---------------------------------------------------------------------------
struct StreamHolder {
    cudaStream_t s = 0;
    cudaEvent_t  evFork = 0, evFork2 = 0, evJoin = 0;
    bool ok = false;
    StreamHolder() {
        ok = (cudaStreamCreateWithFlags(&s, cudaStreamNonBlocking) == cudaSuccess) &&
             (cudaEventCreateWithFlags(&evFork, cudaEventDisableTiming) == cudaSuccess) &&
             (cudaEventCreateWithFlags(&evFork2, cudaEventDisableTiming) == cudaSuccess) &&
             (cudaEventCreateWithFlags(&evJoin, cudaEventDisableTiming) == cudaSuccess);
    }
};
static StreamHolder g_sh;

// ---------------------------------------------------------------------------
// helpers
// ---------------------------------------------------------------------------
__device__ __forceinline__ unsigned smem_u32(const void* p) {
    return (unsigned)__cvta_generic_to_shared(p);
}
__device__ __forceinline__ void ldsm_x4(unsigned* r, unsigned addr) {
    asm volatile("ldmatrix.sync.aligned.m8n8.x4.shared.b16 {%0,%1,%2,%3}, [%4];"
                 : "=r"(r[0]), "=r"(r[1]), "=r"(r[2]), "=r"(r[3]) : "r"(addr));
}
__device__ __forceinline__ void ldsm_x4t(unsigned* r, unsigned addr) {
    asm volatile("ldmatrix.sync.aligned.m8n8.x4.trans.shared.b16 {%0,%1,%2,%3}, [%4];"
                 : "=r"(r[0]), "=r"(r[1]), "=r"(r[2]), "=r"(r[3]) : "r"(addr));
}
__device__ __forceinline__ void mma16816(float* d, const unsigned* a, const unsigned* b) {
    asm volatile(
        "mma.sync.aligned.m16n8k16.row.col.f32.f16.f16.f32 "
        "{%0,%1,%2,%3}, {%4,%5,%6,%7}, {%8,%9}, {%0,%1,%2,%3};"
        : "+f"(d[0]), "+f"(d[1]), "+f"(d[2]), "+f"(d[3])
        : "r"(a[0]), "r"(a[1]), "r"(a[2]), "r"(a[3]), "r"(b[0]), "r"(b[1]));
}
__device__ __forceinline__ __half2 pun_h2(unsigned u) {
    __half2 r;
    *reinterpret_cast<unsigned*>(&r) = u;
    return r;
}
__device__ __forceinline__ unsigned long long pack_edge(float w) {
    return (1ull << 32) |
           (unsigned long long)(unsigned)__float2int_rn(fabsf(w) * FIXSCALE);
}

// ---------------------------------------------------------------------------
// 0) detect int64 vs int32 (1 block)
// ---------------------------------------------------------------------------
__global__ void detect_kernel(const unsigned* __restrict__ raw) {
    __shared__ unsigned sh[256];
    int t = threadIdx.x;
    unsigned v = 0;
    for (int k = t; k < 1024; k += 256) v |= raw[2 * k + 1];
    sh[t] = v;
    __syncthreads();
    for (int s = 128; s > 0; s >>= 1) {
        if (t < s) sh[t] |= sh[t + s];
        __syncthreads();
    }
    if (t == 0) g_is64 = (sh[0] == 0u) ? 1 : 0;
}

// ---------------------------------------------------------------------------
// 1) prep (4 edges/thread, vectorized): 64b reduction per edge; batch conv
// ---------------------------------------------------------------------------
__global__ void prep_kernel(const void* __restrict__ ei,
                            const void* __restrict__ bat,
                            const float* __restrict__ ew,
                            int E, int N) {
    const int tid = blockIdx.x * blockDim.x + threadIdx.x;
    const int is64 = g_is64;
    const int base = tid * 4;
    if (base < E) {
        if (base + 4 <= E) {
            int d0, d1, d2, d3;
            if (is64) {
                const longlong2* p = (const longlong2*)((const long long*)ei + E + base);
                longlong2 a = __ldg(p), c = __ldg(p + 1);
                d0 = (int)a.x; d1 = (int)a.y; d2 = (int)c.x; d3 = (int)c.y;
            } else {
                int4 d = __ldg((const int4*)((const int*)ei + E + base));
                d0 = d.x; d1 = d.y; d2 = d.z; d3 = d.w;
            }
            float4 w = __ldg((const float4*)(ew + base));
            atomicAdd(&g_hd[d0], pack_edge(w.x));
            atomicAdd(&g_hd[d1], pack_edge(w.y));
            atomicAdd(&g_hd[d2], pack_edge(w.z));
            atomicAdd(&g_hd[d3], pack_edge(w.w));
        } else {
            for (int i = base; i < E; i++) {
                int d = is64 ? (int)((const long long*)ei)[E + i]
                             : ((const int*)ei)[E + i];
                atomicAdd(&g_hd[d], pack_edge(ew[i]));
            }
        }
    }
    if (tid < N) {
        if (is64) g_bat[tid] = (int)((const long long*)bat)[tid];
        else      g_bat[tid] = ((const int*)bat)[tid];
    }
}

// ---------------------------------------------------------------------------
// 2) 3-phase scan; scanC also computes dis and ZEROES g_hd for next replay
// ---------------------------------------------------------------------------
__global__ __launch_bounds__(256) void scanA_kernel(int N) {
    __shared__ int sh[256];
    int b = blockIdx.x, t = threadIdx.x;
    int base = b * SCAN_BN + t * 4;
    int s = 0;
#pragma unroll
    for (int j = 0; j < 4; j++) {
        int i = base + j;
        if (i < N) s += (int)(g_hd[i] >> 32);
    }
    sh[t] = s;
    __syncthreads();
    for (int o = 128; o > 0; o >>= 1) {
        if (t < o) sh[t] += sh[t + o];
        __syncthreads();
    }
    if (t == 0) g_bsum[b] = sh[0];
}

__global__ __launch_bounds__(128) void scanB_kernel(int NB, int N) {
    __shared__ int sh[128];
    int t = threadIdx.x;
    int v = (t < NB) ? g_bsum[t] : 0;
    sh[t] = v;
    __syncthreads();
    for (int o = 1; o < 128; o <<= 1) {
        int u = (t >= o) ? sh[t - o] : 0;
        __syncthreads();
        sh[t] += u;
        __syncthreads();
    }
    if (t < NB) g_boff[t] = sh[t] - v;
    if (t == 127) g_rowptr[N] = sh[127];
}

__global__ __launch_bounds__(256) void scanC_kernel(int N) {
    __shared__ int sh[256];
    int b = blockIdx.x, t = threadIdx.x;
    int base = b * SCAN_BN + t * 4;
    int c[4];
    unsigned fdeg[4];
    int s = 0;
#pragma unroll
    for (int j = 0; j < 4; j++) {
        int i = base + j;
        if (i < N) {
            unsigned long long h = g_hd[i];
            g_hd[i] = 0ull;                       // reset for next replay
            c[j] = (int)(h >> 32);
            fdeg[j] = (unsigned)(h & 0xffffffffull);
        } else { c[j] = 0; fdeg[j] = 0u; }
        s += c[j];
    }
    int own = s;
    sh[t] = s;
    __syncthreads();
    for (int o = 1; o < 256; o <<= 1) {
        int u = (t >= o) ? sh[t - o] : 0;
        __syncthreads();
        sh[t] += u;
        __syncthreads();
    }
    int run = g_boff[b] + sh[t] - own;
#pragma unroll
    for (int j = 0; j < 4; j++) {
        int i = base + j;
        if (i < N) {
            g_rowptr[i] = run;
            g_wofs[i]   = run;
            run += c[j];
            g_dis[i] = rsqrtf((float)fdeg[j] * (1.0f / FIXSCALE) + 1.0f);
        }
    }
}

// ---------------------------------------------------------------------------
// 3) CSR placement (4 edges/thread, vectorized): {src, dup-half2(|w|)}
// ---------------------------------------------------------------------------
__global__ void place_kernel(const void* __restrict__ ei,
                             const float* __restrict__ ew, int E) {
    const int tid = blockIdx.x * blockDim.x + threadIdx.x;
    const int base = tid * 4;
    if (base >= E) return;
    const int is64 = g_is64;
    if (base + 4 <= E) {
        int s0, s1, s2, s3, d0, d1, d2, d3;
        if (is64) {
            const longlong2* ps = (const longlong2*)((const long long*)ei + base);
            const longlong2* pd = (const longlong2*)((const long long*)ei + E + base);
            longlong2 a = __ldg(ps), c = __ldg(ps + 1);
            longlong2 e = __ldg(pd), f = __ldg(pd + 1);
            s0 = (int)a.x; s1 = (int)a.y; s2 = (int)c.x; s3 = (int)c.y;
            d0 = (int)e.x; d1 = (int)e.y; d2 = (int)f.x; d3 = (int)f.y;
        } else {
            int4 sv = __ldg((const int4*)((const int*)ei + base));
            int4 dv = __ldg((const int4*)((const int*)ei + E + base));
            s0 = sv.x; s1 = sv.y; s2 = sv.z; s3 = sv.w;
            d0 = dv.x; d1 = dv.y; d2 = dv.z; d3 = dv.w;
        }
        float4 w = __ldg((const float4*)(ew + base));
        unsigned h0 = (unsigned)__half_as_ushort(__float2half(fabsf(w.x)));
        unsigned h1 = (unsigned)__half_as_ushort(__float2half(fabsf(w.y)));
        unsigned h2 = (unsigned)__half_as_ushort(__float2half(fabsf(w.z)));
        unsigned h3 = (unsigned)__half_as_ushort(__float2half(fabsf(w.w)));
        int p0 = atomicAdd(&g_wofs[d0], 1);
        int p1 = atomicAdd(&g_wofs[d1], 1);
        int p2 = atomicAdd(&g_wofs[d2], 1);
        int p3 = atomicAdd(&g_wofs[d3], 1);
        g_csr[p0] = make_int2(s0, (int)(h0 | (h0 << 16)));
        g_csr[p1] = make_int2(s1, (int)(h1 | (h1 << 16)));
        g_csr[p2] = make_int2(s2, (int)(h2 | (h2 << 16)));
        g_csr[p3] = make_int2(s3, (int)(h3 | (h3 << 16)));
    } else {
        for (int i = base; i < E; i++) {
            int s, d;
            if (is64) {
                const long long* p = (const long long*)ei;
                s = (int)p[i]; d = (int)p[E + i];
            } else {
                const int* p = (const int*)ei;
                s = p[i]; d = p[E + i];
            }
            unsigned hw = (unsigned)__half_as_ushort(__float2half(fabsf(ew[i])));
            int pslot = atomicAdd(&g_wofs[d], 1);
            g_csr[pslot] = make_int2(s, (int)(hw | (hw << 16)));
        }
    }
}

// ---------------------------------------------------------------------------
// 4) HMMA GEMM (layer 1 only): xw(fp16, stride 96) = x @ W1, unscaled.
// ---------------------------------------------------------------------------
__global__ __launch_bounds__(256) void gemm1_hmma(
    const float* __restrict__ in, const float* __restrict__ W,
    __half* __restrict__ xw, int N)
{
    constexpr int FIN = 128, FOUT = 96, FOUTP = 96, LDOUT = 96;
    constexpr int KC  = 64;
    constexpr int LDA = KC + 8;
    constexpr int LDB = FOUTP + 8;
    constexpr int NT  = FOUTP / 16;

    __shared__ __half As[128 * LDA];
    __shared__ __half Bs[FIN * LDB];

    const int t    = threadIdx.x;
    const int lane = t & 31;
    const int wid  = t >> 5;
    const int wm   = wid >> 1;
    const int wn   = wid & 1;
    const int rowblk = blockIdx.x * 128;

    float acc[2][NT][4];
#pragma unroll
    for (int mt = 0; mt < 2; mt++)
#pragma unroll
        for (int nt = 0; nt < NT; nt++)
#pragma unroll
            for (int q = 0; q < 4; q++) acc[mt][nt][q] = 0.0f;

    for (int i = t; i < FIN * LDB; i += 256) {
        int r = i / LDB, c = i % LDB;
        __half hv = __float2half(0.f);
        if (c < FOUT) hv = __float2half(W[(size_t)r * FOUT + c]);
        Bs[i] = hv;
    }

#pragma unroll
    for (int k0 = 0; k0 < FIN; k0 += KC) {
        constexpr int V = KC / 4;
        for (int i = t; i < 128 * V; i += 256) {
            int r = i / V, c4 = i % V;
            int n = rowblk + r;
            float4 v = make_float4(0.f, 0.f, 0.f, 0.f);
            if (n < N)
                v = *(const float4*)(in + (size_t)n * FIN + k0 + c4 * 4);
            __half2* dp = (__half2*)&As[r * LDA + c4 * 4];
            dp[0] = __floats2half2_rn(v.x, v.y);
            dp[1] = __floats2half2_rn(v.z, v.w);
        }
        __syncthreads();

#pragma unroll
        for (int ks = 0; ks < KC / 16; ks++) {
            unsigned a[2][4];
#pragma unroll
            for (int mt = 0; mt < 2; mt++) {
                int row = wm * 32 + mt * 16 + (lane & 15);
                int col = ks * 16 + (lane >> 4) * 8;
                ldsm_x4(a[mt], smem_u32(&As[row * LDA + col]));
            }
            unsigned b[NT][2];
#pragma unroll
            for (int np = 0; np < NT / 2; np++) {
                int row = k0 + ks * 16 + (lane & 15);
                int col = wn * (NT * 8) + np * 16 + (lane >> 4) * 8;
                unsigned r4[4];
                ldsm_x4t(r4, smem_u32(&Bs[row * LDB + col]));
                b[2 * np][0]     = r4[0]; b[2 * np][1]     = r4[1];
                b[2 * np + 1][0] = r4[2]; b[2 * np + 1][1] = r4[3];
            }
#pragma unroll
            for (int mt = 0; mt < 2; mt++)
#pragma unroll
                for (int nt = 0; nt < NT; nt++)
                    mma16816(acc[mt][nt], a[mt], b[nt]);
        }
        if (k0 + KC < FIN) __syncthreads();
    }

#pragma unroll
    for (int mt = 0; mt < 2; mt++) {
        int r_lo = rowblk + wm * 32 + mt * 16 + (lane >> 2);
        int r_hi = r_lo + 8;
#pragma unroll
        for (int nt = 0; nt < NT; nt++) {
            int c = wn * (NT * 8) + nt * 8 + (lane & 3) * 2;
            if (r_lo < N)
                *(__half2*)&xw[(size_t)r_lo * LDOUT + c] =
                    __floats2half2_rn(acc[mt][nt][0], acc[mt][nt][1]);
            if (r_hi < N)
                *(__half2*)&xw[(size_t)r_hi * LDOUT + c] =
                    __floats2half2_rn(acc[mt][nt][2], acc[mt][nt][3]);
        }
    }
}

// ---------------------------------------------------------------------------
// 5) xwscale: xw'[n] = dis[n] * xw[n]  (in-place, runs on side stream)
// ---------------------------------------------------------------------------
__global__ void xwscale_kernel(__half2* __restrict__ xw, int N) {
    int idx = blockIdx.x * blockDim.x + threadIdx.x;
    int n = idx / 12;
    if (n >= N) return;
    int c = idx % 12;
    uint4* p = (uint4*)xw + (size_t)n * 12 + c;
    uint4 v = *p;
    float d = __ldg(&g_dis[n]);
    __half2 dh = __floats2half2_rn(d, d);
    __half2* h = (__half2*)&v;
    h[0] = __hmul2(h[0], dh); h[1] = __hmul2(h[1], dh);
    h[2] = __hmul2(h[2], dh); h[3] = __hmul2(h[3], dh);
    *p = v;
}

// ---------------------------------------------------------------------------
// 6) FUSED gather96 + next-layer GEMM. Block = 128 nodes, 8 warps.
// ---------------------------------------------------------------------------
template<int FOUT, int FOUTP, int LDOUT>
__global__ __launch_bounds__(256) void fused_gg_kernel(
    const __half2* __restrict__ xwp, const float* __restrict__ b,
    const float* __restrict__ W, __half* __restrict__ xwout, int N)
{
    constexpr int FIN = 96;
    constexpr int LDA = FIN + 8;       // 104
    constexpr int LDB = FOUTP + 8;
    constexpr int NT  = FOUTP / 16;

    __shared__ __half actS[128 * LDA];
    __shared__ __half Bs[FIN * LDB];

    const int t    = threadIdx.x;
    const int lane = t & 31;
    const int wid  = t >> 5;
    const int hl   = lane & 15;
    const int hh   = lane >> 4;
    const int rowblk = blockIdx.x * 128;

    for (int i = t; i < FIN * LDB; i += 256) {
        int r = i / LDB, c = i % LDB;
        __half hv = __float2half(0.f);
        if (c < FOUT) hv = __float2half(W[(size_t)r * FOUT + c]);
        Bs[i] = hv;
    }

    const uint4* __restrict__ xw4 = (const uint4*)xwp;
    const __half2 hz = __floats2half2_rn(0.f, 0.f);
    const bool ld = (hl < 12);

    for (int p = 0; p < 8; p++) {
        const int nloc = (p * 8 + wid) * 2 + hh;
        const int n = rowblk + nloc;
        const bool valid_n = (n < N);

        int beg = 0, len = 0;
        if (valid_n) {
            beg = g_rowptr[n];
            len = g_rowptr[n + 1] - beg;
        }
        const int lenOther = __shfl_xor_sync(0xffffffffu, len, 16);
        const int lenMax = max(len, lenOther);
        const int last = (len > 0) ? (beg + len - 1) : 0;

        float accf[8];
#pragma unroll
        for (int j = 0; j < 8; j++) accf[j] = 0.f;

        int2 cv[4];
#pragma unroll
        for (int i = 0; i < 4; i++) {
            int idx = beg + i;
            idx = (idx <= last) ? idx : last;
            cv[i] = __ldg(&g_csr[idx]);
        }

        for (int k = 0; k < lenMax; k += 4) {
            uint4 u[4];
            __half2 vv[4];
#pragma unroll
            for (int i = 0; i < 4; i++) {
                vv[i] = (k + i < len) ? pun_h2((unsigned)cv[i].y) : hz;
                u[i] = ld ? __ldg(xw4 + (size_t)cv[i].x * 12 + hl)
                          : make_uint4(0u, 0u, 0u, 0u);
            }
#pragma unroll
            for (int i = 0; i < 4; i++) {
                int idx = beg + k + 4 + i;
                idx = (idx <= last) ? idx : last;
                cv[i] = __ldg(&g_csr[idx]);
            }
            __half2 a0 = hz, a1 = hz, a2 = hz, a3 = hz;
#pragma unroll
            for (int i = 0; i < 4; i++) {
                const __half2* h = (const __half2*)&u[i];
                a0 = __hfma2(vv[i], h[0], a0);
                a1 = __hfma2(vv[i], h[1], a1);
                a2 = __hfma2(vv[i], h[2], a2);
                a3 = __hfma2(vv[i], h[3], a3);
            }
            float2 f;
            f = __half22float2(a0); accf[0] += f.x; accf[1] += f.y;
            f = __half22float2(a1); accf[2] += f.x; accf[3] += f.y;
            f = __half22float2(a2); accf[4] += f.x; accf[5] += f.y;
            f = __half22float2(a3); accf[6] += f.x; accf[7] += f.y;
        }

        if (ld) {
            float d = 0.f;
            uint4 su = make_uint4(0u, 0u, 0u, 0u);
            if (valid_n) {
                d = g_dis[n];
                su = __ldg(xw4 + (size_t)n * 12 + hl);
            }
            const __half2* sh = (const __half2*)&su;
            float4 b0 = *(const float4*)(b + hl * 8);
            float4 b1 = *(const float4*)(b + hl * 8 + 4);
            __half2 o[4];
            float2 s;
            s = __half22float2(sh[0]);
            o[0] = __floats2half2_rn(fmaxf(d * (accf[0] + s.x) + b0.x, 0.f),
                                     fmaxf(d * (accf[1] + s.y) + b0.y, 0.f));
            s = __half22float2(sh[1]);
            o[1] = __floats2half2_rn(fmaxf(d * (accf[2] + s.x) + b0.z, 0.f),
                                     fmaxf(d * (accf[3] + s.y) + b0.w, 0.f));
            s = __half22float2(sh[2]);
            o[2] = __floats2half2_rn(fmaxf(d * (accf[4] + s.x) + b1.x, 0.f),
                                     fmaxf(d * (accf[5] + s.y) + b1.y, 0.f));
            s = __half22float2(sh[3]);
            o[3] = __floats2half2_rn(fmaxf(d * (accf[6] + s.x) + b1.z, 0.f),
                                     fmaxf(d * (accf[7] + s.y) + b1.w, 0.f));
            *(uint4*)&actS[nloc * LDA + hl * 8] = *(const uint4*)o;
        }
    }
    __syncthreads();

    const int wm = wid >> 1;
    const int wn = wid & 1;
    float acc[2][NT][4];
#pragma unroll
    for (int mt = 0; mt < 2; mt++)
#pragma unroll
        for (int nt = 0; nt < NT; nt++)
#pragma unroll
            for (int q = 0; q < 4; q++) acc[mt][nt][q] = 0.0f;

#pragma unroll
    for (int ks = 0; ks < FIN / 16; ks++) {
        unsigned a[2][4];
#pragma unroll
        for (int mt = 0; mt < 2; mt++) {
            int row = wm * 32 + mt * 16 + (lane & 15);
            int col = ks * 16 + (lane >> 4) * 8;
            ldsm_x4(a[mt], smem_u32(&actS[row * LDA + col]));
        }
        unsigned bb[NT][2];
#pragma unroll
        for (int np = 0; np < NT / 2; np++) {
            int row = ks * 16 + (lane & 15);
            int col = wn * (NT * 8) + np * 16 + (lane >> 4) * 8;
            unsigned r4[4];
            ldsm_x4t(r4, smem_u32(&Bs[row * LDB + col]));
            bb[2 * np][0]     = r4[0]; bb[2 * np][1]     = r4[1];
            bb[2 * np + 1][0] = r4[2]; bb[2 * np + 1][1] = r4[3];
        }
#pragma unroll
        for (int mt = 0; mt < 2; mt++)
#pragma unroll
            for (int nt = 0; nt < NT; nt++)
                mma16816(acc[mt][nt], a[mt], bb[nt]);
    }

#pragma unroll
    for (int mt = 0; mt < 2; mt++) {
        int r_lo = rowblk + wm * 32 + mt * 16 + (lane >> 2);
        int r_hi = r_lo + 8;
        float dl = (r_lo < N) ? g_dis[r_lo] : 0.f;
        float dh = (r_hi < N) ? g_dis[r_hi] : 0.f;
#pragma unroll
        for (int nt = 0; nt < NT; nt++) {
            int c = wn * (NT * 8) + nt * 8 + (lane & 3) * 2;
            if (r_lo < N)
                *(__half2*)&xwout[(size_t)r_lo * LDOUT + c] =
                    __floats2half2_rn(dl * acc[mt][nt][0], dl * acc[mt][nt][1]);
            if (r_hi < N)
                *(__half2*)&xwout[(size_t)r_hi * LDOUT + c] =
                    __floats2half2_rn(dh * acc[mt][nt][2], dh * acc[mt][nt][3]);
        }
    }
}

// ---------------------------------------------------------------------------
// 7) Gather30 + relu + mean-pool atomics (xw3' is dis-scaled; stride 32)
// ---------------------------------------------------------------------------
__global__ __launch_bounds__(256) void gather30_kernel(
    const __half2* __restrict__ xw, const float* __restrict__ b, int N)
{
    const int lane = threadIdx.x & 31;
    const int hl = lane & 15;
    const int hh = lane >> 4;
    const int n = (((blockIdx.x * blockDim.x + threadIdx.x) >> 5) << 1) + hh;
    const bool valid_n = (n < N);

    int beg = 0, len = 0;
    if (valid_n) {
        beg = g_rowptr[n];
        len = g_rowptr[n + 1] - beg;
    }
    const int lenOther = __shfl_xor_sync(0xffffffffu, len, 16);
    const int lenMax = max(len, lenOther);
    const int last = (len > 0) ? (beg + len - 1) : 0;

    float ax = 0.f, ay = 0.f;
    const __half2 hz = __floats2half2_rn(0.f, 0.f);

    int2 cv[4];
#pragma unroll
    for (int i = 0; i < 4; i++) {
        int idx = beg + i;
        idx = (idx <= last) ? idx : last;
        cv[i] = __ldg(&g_csr[idx]);
    }

    for (int k = 0; k < lenMax; k += 4) {
        __half2 u[4], vv[4];
#pragma unroll
        for (int i = 0; i < 4; i++) {
            vv[i] = (k + i < len) ? pun_h2((unsigned)cv[i].y) : hz;
            u[i] = __ldg(xw + (size_t)cv[i].x * 16 + hl);
        }
#pragma unroll
        for (int i = 0; i < 4; i++) {
            int idx = beg + k + 4 + i;
            idx = (idx <= last) ? idx : last;
            cv[i] = __ldg(&g_csr[idx]);
        }
        __half2 a0 = hz;
#pragma unroll
        for (int i = 0; i < 4; i++) a0 = __hfma2(vv[i], u[i], a0);
        float2 f = __half22float2(a0);
        ax += f.x; ay += f.y;
    }

    if (valid_n) {
        const float d = g_dis[n];
        const int g = g_bat[n];
        if (hl < 15) {
            float2 s = __half22float2(__ldg(xw + (size_t)n * 16 + hl));
            float2 bb = *(const float2*)(b + 2 * hl);
            float v0 = fmaxf(d * (ax + s.x) + bb.x, 0.f);
            float v1 = fmaxf(d * (ay + s.y) + bb.y, 0.f);
            atomicAdd(&g_pool[g * F3 + 2 * hl],     v0);
            atomicAdd(&g_pool[g * F3 + 2 * hl + 1], v1);
        } else {
            atomicAdd(&g_cnt[g], 1.0f);
        }
    }
}

// ---------------------------------------------------------------------------
// 8) classifier + softmax; resets pool/cnt for next graph replay
// ---------------------------------------------------------------------------
__global__ void final_kernel(const float* __restrict__ Wf,
                             const float* __restrict__ bf,
                             float* __restrict__ out) {
    int g = threadIdx.x;
    if (g >= G_MAX) return;
    float cnt = fmaxf(g_cnt[g], 1.0f);
    float p[F3];
#pragma unroll
    for (int j = 0; j < F3; j++) p[j] = g_pool[g * F3 + j] / cnt;
    float lo[NCLS];
    float m = -1e30f;
#pragma unroll
    for (int k = 0; k < NCLS; k++) {
        float s = bf[k];
#pragma unroll
        for (int j = 0; j < F3; j++) s += p[j] * Wf[j * NCLS + k];
        lo[k] = s;
        m = fmaxf(m, s);
    }
    float sum = 0.0f;
#pragma unroll
    for (int k = 0; k < NCLS; k++) { lo[k] = expf(lo[k] - m); sum += lo[k]; }
    float inv = 1.0f / sum;
#pragma unroll
    for (int k = 0; k < NCLS; k++) out[g * NCLS + k] = lo[k] * inv;
#pragma unroll
    for (int j = 0; j < F3; j++) g_pool[g * F3 + j] = 0.0f;
    g_cnt[g] = 0.0f;
}

// ---------------------------------------------------------------------------
// Launch
// ---------------------------------------------------------------------------
extern "C" void kernel_launch(void* const* d_in, const int* in_sizes, int n_in,
                              void* d_out, int out_size) {
    const float* x   = (const float*)d_in[0];
    const void*  ei  = d_in[1];
    const float* ew  = (const float*)d_in[2];
    const void*  bat = d_in[3];
    const float* W1  = (const float*)d_in[4];
    const float* b1  = (const float*)d_in[5];
    const float* W2  = (const float*)d_in[6];
    const float* b2  = (const float*)d_in[7];
    const float* W3  = (const float*)d_in[8];
    const float* b3  = (const float*)d_in[9];
    const float* Wf  = (const float*)d_in[10];
    const float* bf  = (const float*)d_in[11];
    float* out = (float*)d_out;

    const int E = in_sizes[2];
    const int N = in_sizes[3];

    __half *pXW, *pXW2;
    cudaGetSymbolAddress((void**)&pXW,  g_xw);
    cudaGetSymbolAddress((void**)&pXW2, g_xw2);

    const int TB = 256;
    const int E4 = (E + 3) / 4;
    const int gPrep = (max(E4, N) + TB - 1) / TB;
    const int gPlace = (E4 + TB - 1) / TB;
    const int gGemm = (N + 127) / 128;
    const int gGather = ((N + 1) / 2 * 32 + TB - 1) / TB;
    const int gScale = (N * 12 + TB - 1) / TB;
    const int NB = (N + SCAN_BN - 1) / SCAN_BN;

    const bool fork = g_sh.ok;
    if (fork) {
        cudaEventRecord(g_sh.evFork, 0);
        cudaStreamWaitEvent(g_sh.s, g_sh.evFork, 0);
        gemm1_hmma<<<gGemm, TB, 0, g_sh.s>>>(x, W1, pXW, N);
    }

    detect_kernel<<<1, 256>>>((const unsigned*)ei);
    prep_kernel<<<gPrep, TB>>>(ei, bat, ew, E, N);
    scanA_kernel<<<NB, 256>>>(N);
    scanB_kernel<<<1, 128>>>(NB, N);
    scanC_kernel<<<NB, 256>>>(N);

    if (fork) {
        cudaEventRecord(g_sh.evFork2, 0);
        cudaStreamWaitEvent(g_sh.s, g_sh.evFork2, 0);
        xwscale_kernel<<<gScale, TB, 0, g_sh.s>>>((__half2*)pXW, N);
        cudaEventRecord(g_sh.evJoin, g_sh.s);
    }

    place_kernel<<<gPlace, TB>>>(ei, ew, E);

    if (fork) {
        cudaStreamWaitEvent(0, g_sh.evJoin, 0);
    } else {
        gemm1_hmma<<<gGemm, TB>>>(x, W1, pXW, N);
        xwscale_kernel<<<gScale, TB>>>((__half2*)pXW, N);
    }

    fused_gg_kernel<96, 96, 96><<<gGemm, TB>>>(
        (const __half2*)pXW, b1, W2, pXW2, N);
    fused_gg_kernel<30, 32, 32><<<gGemm, TB>>>(
        (const __half2*)pXW2, b2, W3, pXW, N);

    gather30_kernel<<<gGather, TB>>>((const __half2*)pXW, b3, N);
    final_kernel<<<1, 256>>>(Wf, bf, out);

    (void)n_in; (void)out_size;
}

// round 12
// speedup vs baseline: 1.0294x; 1.0294x over previous
#include <cuda_runtime.h>
#include <cuda_fp16.h>
#include <math.h>

#define N_MAX   100000
#define E_MAX   3200000
#define G_MAX   256
#define F3      30
#define NCLS    10

#define FIXSCALE 1048576.0f     // 2^20 fixed point for |w| degree accumulation
#define SCAN_BN  1024
#define SCAN_MAXB 128

// ---------------------------------------------------------------------------
// Device scratch (zero at module load; self-resetting across graph replays)
// ---------------------------------------------------------------------------
__device__ int                g_is64;
__device__ int                g_bat[N_MAX];
__device__ float              g_dis[N_MAX];     // D^{-1/2}
__device__ unsigned long long g_hd[N_MAX];      // (count<<32)|fixed_deg; zeroed on consume
__device__ int                g_rowptr[N_MAX + 1];
__device__ int                g_bsum[SCAN_MAXB];
__device__ int                g_boff[SCAN_MAXB];
__device__ unsigned           g_rank[E_MAX];    // (rank<<16)|half(|w|) per edge
__device__ int2               g_csr[E_MAX];     // {src, half2(|w|,|w|)}
__device__ __half             g_xw[N_MAX * 96]; // layer-1 xw' (also reused for xw3')
__device__ __half             g_xw2[N_MAX * 96];
__device__ float              g_pool[G_MAX * F3];   // zeroed by final after use
__device__ float              g_cnt[G_MAX];

// ---------------------------------------------------------------------------
// Side stream + events (static init, before harness memory checkpoints)
// ---------------------------------------------------------------------------
struct StreamHolder {
    cudaStream_t s = 0;
    cudaEvent_t  evFork = 0, evFork2 = 0, evJoin = 0;
    bool ok = false;
    StreamHolder() {
        ok = (cudaStreamCreateWithFlags(&s, cudaStreamNonBlocking) == cudaSuccess) &&
             (cudaEventCreateWithFlags(&evFork, cudaEventDisableTiming) == cudaSuccess) &&
             (cudaEventCreateWithFlags(&evFork2, cudaEventDisableTiming) == cudaSuccess) &&
             (cudaEventCreateWithFlags(&evJoin, cudaEventDisableTiming) == cudaSuccess);
    }
};
static StreamHolder g_sh;

// ---------------------------------------------------------------------------
// helpers
// ---------------------------------------------------------------------------
__device__ __forceinline__ unsigned smem_u32(const void* p) {
    return (unsigned)__cvta_generic_to_shared(p);
}
__device__ __forceinline__ void ldsm_x4(unsigned* r, unsigned addr) {
    asm volatile("ldmatrix.sync.aligned.m8n8.x4.shared.b16 {%0,%1,%2,%3}, [%4];"
                 : "=r"(r[0]), "=r"(r[1]), "=r"(r[2]), "=r"(r[3]) : "r"(addr));
}
__device__ __forceinline__ void ldsm_x4t(unsigned* r, unsigned addr) {
    asm volatile("ldmatrix.sync.aligned.m8n8.x4.trans.shared.b16 {%0,%1,%2,%3}, [%4];"
                 : "=r"(r[0]), "=r"(r[1]), "=r"(r[2]), "=r"(r[3]) : "r"(addr));
}
__device__ __forceinline__ void mma16816(float* d, const unsigned* a, const unsigned* b) {
    asm volatile(
        "mma.sync.aligned.m16n8k16.row.col.f32.f16.f16.f32 "
        "{%0,%1,%2,%3}, {%4,%5,%6,%7}, {%8,%9}, {%0,%1,%2,%3};"
        : "+f"(d[0]), "+f"(d[1]), "+f"(d[2]), "+f"(d[3])
        : "r"(a[0]), "r"(a[1]), "r"(a[2]), "r"(a[3]), "r"(b[0]), "r"(b[1]));
}
__device__ __forceinline__ __half2 pun_h2(unsigned u) {
    __half2 r;
    *reinterpret_cast<unsigned*>(&r) = u;
    return r;
}
__device__ __forceinline__ unsigned half_bits(float w) {
    return (unsigned)__half_as_ushort(__float2half(fabsf(w)));
}
__device__ __forceinline__ unsigned long long pack_edge(float w) {
    return (1ull << 32) |
           (unsigned long long)(unsigned)__float2int_rn(fabsf(w) * FIXSCALE);
}

// ---------------------------------------------------------------------------
// 0) detect int64 vs int32 (1 block)
// ---------------------------------------------------------------------------
__global__ void detect_kernel(const unsigned* __restrict__ raw) {
    __shared__ unsigned sh[256];
    int t = threadIdx.x;
    unsigned v = 0;
    for (int k = t; k < 1024; k += 256) v |= raw[2 * k + 1];
    sh[t] = v;
    __syncthreads();
    for (int s = 128; s > 0; s >>= 1) {
        if (t < s) sh[t] |= sh[t + s];
        __syncthreads();
    }
    if (t == 0) g_is64 = (sh[0] == 0u) ? 1 : 0;
}

// ---------------------------------------------------------------------------
// 1) prep (4 edges/thread): 64b reduction per edge; ALSO captures each edge's
//    rank within its dst row from the atomic return (free slot assignment)
//    and stores (rank<<16)|half(|w|). Batch conversion piggybacked.
// ---------------------------------------------------------------------------
__global__ void prep_kernel(const void* __restrict__ ei,
                            const void* __restrict__ bat,
                            const float* __restrict__ ew,
                            int E, int N) {
    const int tid = blockIdx.x * blockDim.x + threadIdx.x;
    const int is64 = g_is64;
    const int base = tid * 4;
    if (base < E) {
        if (base + 4 <= E) {
            int d0, d1, d2, d3;
            if (is64) {
                const longlong2* p = (const longlong2*)((const long long*)ei + E + base);
                longlong2 a = __ldg(p), c = __ldg(p + 1);
                d0 = (int)a.x; d1 = (int)a.y; d2 = (int)c.x; d3 = (int)c.y;
            } else {
                int4 d = __ldg((const int4*)((const int*)ei + E + base));
                d0 = d.x; d1 = d.y; d2 = d.z; d3 = d.w;
            }
            float4 w = __ldg((const float4*)(ew + base));
            unsigned long long o0 = atomicAdd(&g_hd[d0], pack_edge(w.x));
            unsigned long long o1 = atomicAdd(&g_hd[d1], pack_edge(w.y));
            unsigned long long o2 = atomicAdd(&g_hd[d2], pack_edge(w.z));
            unsigned long long o3 = atomicAdd(&g_hd[d3], pack_edge(w.w));
            uint4 rk;
            rk.x = ((unsigned)(o0 >> 32) << 16) | half_bits(w.x);
            rk.y = ((unsigned)(o1 >> 32) << 16) | half_bits(w.y);
            rk.z = ((unsigned)(o2 >> 32) << 16) | half_bits(w.z);
            rk.w = ((unsigned)(o3 >> 32) << 16) | half_bits(w.w);
            *(uint4*)(g_rank + base) = rk;
        } else {
            for (int i = base; i < E; i++) {
                int d = is64 ? (int)((const long long*)ei)[E + i]
                             : ((const int*)ei)[E + i];
                float w = ew[i];
                unsigned long long o = atomicAdd(&g_hd[d], pack_edge(w));
                g_rank[i] = ((unsigned)(o >> 32) << 16) | half_bits(w);
            }
        }
    }
    if (tid < N) {
        if (is64) g_bat[tid] = (int)((const long long*)bat)[tid];
        else      g_bat[tid] = ((const int*)bat)[tid];
    }
}

// ---------------------------------------------------------------------------
// 2) 3-phase scan; scanC also computes dis and ZEROES g_hd for next replay
// ---------------------------------------------------------------------------
__global__ __launch_bounds__(256) void scanA_kernel(int N) {
    __shared__ int sh[256];
    int b = blockIdx.x, t = threadIdx.x;
    int base = b * SCAN_BN + t * 4;
    int s = 0;
#pragma unroll
    for (int j = 0; j < 4; j++) {
        int i = base + j;
        if (i < N) s += (int)(g_hd[i] >> 32);
    }
    sh[t] = s;
    __syncthreads();
    for (int o = 128; o > 0; o >>= 1) {
        if (t < o) sh[t] += sh[t + o];
        __syncthreads();
    }
    if (t == 0) g_bsum[b] = sh[0];
}

__global__ __launch_bounds__(128) void scanB_kernel(int NB, int N) {
    __shared__ int sh[128];
    int t = threadIdx.x;
    int v = (t < NB) ? g_bsum[t] : 0;
    sh[t] = v;
    __syncthreads();
    for (int o = 1; o < 128; o <<= 1) {
        int u = (t >= o) ? sh[t - o] : 0;
        __syncthreads();
        sh[t] += u;
        __syncthreads();
    }
    if (t < NB) g_boff[t] = sh[t] - v;
    if (t == 127) g_rowptr[N] = sh[127];
}

__global__ __launch_bounds__(256) void scanC_kernel(int N) {
    __shared__ int sh[256];
    int b = blockIdx.x, t = threadIdx.x;
    int base = b * SCAN_BN + t * 4;
    int c[4];
    unsigned fdeg[4];
    int s = 0;
#pragma unroll
    for (int j = 0; j < 4; j++) {
        int i = base + j;
        if (i < N) {
            unsigned long long h = g_hd[i];
            g_hd[i] = 0ull;                       // reset for next replay
            c[j] = (int)(h >> 32);
            fdeg[j] = (unsigned)(h & 0xffffffffull);
        } else { c[j] = 0; fdeg[j] = 0u; }
        s += c[j];
    }
    int own = s;
    sh[t] = s;
    __syncthreads();
    for (int o = 1; o < 256; o <<= 1) {
        int u = (t >= o) ? sh[t - o] : 0;
        __syncthreads();
        sh[t] += u;
        __syncthreads();
    }
    int run = g_boff[b] + sh[t] - own;
#pragma unroll
    for (int j = 0; j < 4; j++) {
        int i = base + j;
        if (i < N) {
            g_rowptr[i] = run;
            run += c[j];
            g_dis[i] = rsqrtf((float)fdeg[j] * (1.0f / FIXSCALE) + 1.0f);
        }
    }
}

// ---------------------------------------------------------------------------
// 3) CSR placement, ATOMIC-FREE: slot = rowptr[dst] + rank (from prep).
// ---------------------------------------------------------------------------
__global__ void place_kernel(const void* __restrict__ ei, int E) {
    const int tid = blockIdx.x * blockDim.x + threadIdx.x;
    const int base = tid * 4;
    if (base >= E) return;
    const int is64 = g_is64;
    if (base + 4 <= E) {
        int s0, s1, s2, s3, d0, d1, d2, d3;
        if (is64) {
            const longlong2* ps = (const longlong2*)((const long long*)ei + base);
            const longlong2* pd = (const longlong2*)((const long long*)ei + E + base);
            longlong2 a = __ldg(ps), c = __ldg(ps + 1);
            longlong2 e = __ldg(pd), f = __ldg(pd + 1);
            s0 = (int)a.x; s1 = (int)a.y; s2 = (int)c.x; s3 = (int)c.y;
            d0 = (int)e.x; d1 = (int)e.y; d2 = (int)f.x; d3 = (int)f.y;
        } else {
            int4 sv = __ldg((const int4*)((const int*)ei + base));
            int4 dv = __ldg((const int4*)((const int*)ei + E + base));
            s0 = sv.x; s1 = sv.y; s2 = sv.z; s3 = sv.w;
            d0 = dv.x; d1 = dv.y; d2 = dv.z; d3 = dv.w;
        }
        uint4 rk = *(const uint4*)(g_rank + base);
        int p0 = __ldg(&g_rowptr[d0]) + (int)(rk.x >> 16);
        int p1 = __ldg(&g_rowptr[d1]) + (int)(rk.y >> 16);
        int p2 = __ldg(&g_rowptr[d2]) + (int)(rk.z >> 16);
        int p3 = __ldg(&g_rowptr[d3]) + (int)(rk.w >> 16);
        unsigned h0 = rk.x & 0xffffu, h1 = rk.y & 0xffffu;
        unsigned h2 = rk.z & 0xffffu, h3 = rk.w & 0xffffu;
        g_csr[p0] = make_int2(s0, (int)(h0 | (h0 << 16)));
        g_csr[p1] = make_int2(s1, (int)(h1 | (h1 << 16)));
        g_csr[p2] = make_int2(s2, (int)(h2 | (h2 << 16)));
        g_csr[p3] = make_int2(s3, (int)(h3 | (h3 << 16)));
    } else {
        for (int i = base; i < E; i++) {
            int s, d;
            if (is64) {
                const long long* p = (const long long*)ei;
                s = (int)p[i]; d = (int)p[E + i];
            } else {
                const int* p = (const int*)ei;
                s = p[i]; d = p[E + i];
            }
            unsigned rk = g_rank[i];
            int pslot = g_rowptr[d] + (int)(rk >> 16);
            unsigned hw = rk & 0xffffu;
            g_csr[pslot] = make_int2(s, (int)(hw | (hw << 16)));
        }
    }
}

// ---------------------------------------------------------------------------
// 4) HMMA GEMM (layer 1 only): xw(fp16, stride 96) = x @ W1, unscaled.
// ---------------------------------------------------------------------------
__global__ __launch_bounds__(256) void gemm1_hmma(
    const float* __restrict__ in, const float* __restrict__ W,
    __half* __restrict__ xw, int N)
{
    constexpr int FIN = 128, FOUT = 96, FOUTP = 96, LDOUT = 96;
    constexpr int KC  = 64;
    constexpr int LDA = KC + 8;
    constexpr int LDB = FOUTP + 8;
    constexpr int NT  = FOUTP / 16;

    __shared__ __half As[128 * LDA];
    __shared__ __half Bs[FIN * LDB];

    const int t    = threadIdx.x;
    const int lane = t & 31;
    const int wid  = t >> 5;
    const int wm   = wid >> 1;
    const int wn   = wid & 1;
    const int rowblk = blockIdx.x * 128;

    float acc[2][NT][4];
#pragma unroll
    for (int mt = 0; mt < 2; mt++)
#pragma unroll
        for (int nt = 0; nt < NT; nt++)
#pragma unroll
            for (int q = 0; q < 4; q++) acc[mt][nt][q] = 0.0f;

    for (int i = t; i < FIN * LDB; i += 256) {
        int r = i / LDB, c = i % LDB;
        __half hv = __float2half(0.f);
        if (c < FOUT) hv = __float2half(W[(size_t)r * FOUT + c]);
        Bs[i] = hv;
    }

#pragma unroll
    for (int k0 = 0; k0 < FIN; k0 += KC) {
        constexpr int V = KC / 4;
        for (int i = t; i < 128 * V; i += 256) {
            int r = i / V, c4 = i % V;
            int n = rowblk + r;
            float4 v = make_float4(0.f, 0.f, 0.f, 0.f);
            if (n < N)
                v = *(const float4*)(in + (size_t)n * FIN + k0 + c4 * 4);
            __half2* dp = (__half2*)&As[r * LDA + c4 * 4];
            dp[0] = __floats2half2_rn(v.x, v.y);
            dp[1] = __floats2half2_rn(v.z, v.w);
        }
        __syncthreads();

#pragma unroll
        for (int ks = 0; ks < KC / 16; ks++) {
            unsigned a[2][4];
#pragma unroll
            for (int mt = 0; mt < 2; mt++) {
                int row = wm * 32 + mt * 16 + (lane & 15);
                int col = ks * 16 + (lane >> 4) * 8;
                ldsm_x4(a[mt], smem_u32(&As[row * LDA + col]));
            }
            unsigned b[NT][2];
#pragma unroll
            for (int np = 0; np < NT / 2; np++) {
                int row = k0 + ks * 16 + (lane & 15);
                int col = wn * (NT * 8) + np * 16 + (lane >> 4) * 8;
                unsigned r4[4];
                ldsm_x4t(r4, smem_u32(&Bs[row * LDB + col]));
                b[2 * np][0]     = r4[0]; b[2 * np][1]     = r4[1];
                b[2 * np + 1][0] = r4[2]; b[2 * np + 1][1] = r4[3];
            }
#pragma unroll
            for (int mt = 0; mt < 2; mt++)
#pragma unroll
                for (int nt = 0; nt < NT; nt++)
                    mma16816(acc[mt][nt], a[mt], b[nt]);
        }
        if (k0 + KC < FIN) __syncthreads();
    }

#pragma unroll
    for (int mt = 0; mt < 2; mt++) {
        int r_lo = rowblk + wm * 32 + mt * 16 + (lane >> 2);
        int r_hi = r_lo + 8;
#pragma unroll
        for (int nt = 0; nt < NT; nt++) {
            int c = wn * (NT * 8) + nt * 8 + (lane & 3) * 2;
            if (r_lo < N)
                *(__half2*)&xw[(size_t)r_lo * LDOUT + c] =
                    __floats2half2_rn(acc[mt][nt][0], acc[mt][nt][1]);
            if (r_hi < N)
                *(__half2*)&xw[(size_t)r_hi * LDOUT + c] =
                    __floats2half2_rn(acc[mt][nt][2], acc[mt][nt][3]);
        }
    }
}

// ---------------------------------------------------------------------------
// 5) xwscale: xw'[n] = dis[n] * xw[n]  (in-place, runs on side stream)
// ---------------------------------------------------------------------------
__global__ void xwscale_kernel(__half2* __restrict__ xw, int N) {
    int idx = blockIdx.x * blockDim.x + threadIdx.x;
    int n = idx / 12;
    if (n >= N) return;
    int c = idx % 12;
    uint4* p = (uint4*)xw + (size_t)n * 12 + c;
    uint4 v = *p;
    float d = __ldg(&g_dis[n]);
    __half2 dh = __floats2half2_rn(d, d);
    __half2* h = (__half2*)&v;
    h[0] = __hmul2(h[0], dh); h[1] = __hmul2(h[1], dh);
    h[2] = __hmul2(h[2], dh); h[3] = __hmul2(h[3], dh);
    *p = v;
}

// ---------------------------------------------------------------------------
// 6) FUSED gather96 + next-layer GEMM. Block = 128 nodes, 8 warps.
//    min 3 blocks/SM to keep gather-phase warp parallelism.
// ---------------------------------------------------------------------------
template<int FOUT, int FOUTP, int LDOUT>
__global__ __launch_bounds__(256, 3) void fused_gg_kernel(
    const __half2* __restrict__ xwp, const float* __restrict__ b,
    const float* __restrict__ W, __half* __restrict__ xwout, int N)
{
    constexpr int FIN = 96;
    constexpr int LDA = FIN + 8;       // 104
    constexpr int LDB = FOUTP + 8;
    constexpr int NT  = FOUTP / 16;

    __shared__ __half actS[128 * LDA];
    __shared__ __half Bs[FIN * LDB];

    const int t    = threadIdx.x;
    const int lane = t & 31;
    const int wid  = t >> 5;
    const int hl   = lane & 15;
    const int hh   = lane >> 4;
    const int rowblk = blockIdx.x * 128;

    for (int i = t; i < FIN * LDB; i += 256) {
        int r = i / LDB, c = i % LDB;
        __half hv = __float2half(0.f);
        if (c < FOUT) hv = __float2half(W[(size_t)r * FOUT + c]);
        Bs[i] = hv;
    }

    const uint4* __restrict__ xw4 = (const uint4*)xwp;
    const __half2 hz = __floats2half2_rn(0.f, 0.f);
    const bool ld = (hl < 12);

    for (int p = 0; p < 8; p++) {
        const int nloc = (p * 8 + wid) * 2 + hh;
        const int n = rowblk + nloc;
        const bool valid_n = (n < N);

        int beg = 0, len = 0;
        if (valid_n) {
            beg = g_rowptr[n];
            len = g_rowptr[n + 1] - beg;
        }
        const int lenOther = __shfl_xor_sync(0xffffffffu, len, 16);
        const int lenMax = max(len, lenOther);
        const int last = (len > 0) ? (beg + len - 1) : 0;

        float accf[8];
#pragma unroll
        for (int j = 0; j < 8; j++) accf[j] = 0.f;

        int2 cv[4];
#pragma unroll
        for (int i = 0; i < 4; i++) {
            int idx = beg + i;
            idx = (idx <= last) ? idx : last;
            cv[i] = __ldg(&g_csr[idx]);
        }

        for (int k = 0; k < lenMax; k += 4) {
            uint4 u[4];
            __half2 vv[4];
#pragma unroll
            for (int i = 0; i < 4; i++) {
                vv[i] = (k + i < len) ? pun_h2((unsigned)cv[i].y) : hz;
                u[i] = ld ? __ldg(xw4 + (size_t)cv[i].x * 12 + hl)
                          : make_uint4(0u, 0u, 0u, 0u);
            }
#pragma unroll
            for (int i = 0; i < 4; i++) {
                int idx = beg + k + 4 + i;
                idx = (idx <= last) ? idx : last;
                cv[i] = __ldg(&g_csr[idx]);
            }
            __half2 a0 = hz, a1 = hz, a2 = hz, a3 = hz;
#pragma unroll
            for (int i = 0; i < 4; i++) {
                const __half2* h = (const __half2*)&u[i];
                a0 = __hfma2(vv[i], h[0], a0);
                a1 = __hfma2(vv[i], h[1], a1);
                a2 = __hfma2(vv[i], h[2], a2);
                a3 = __hfma2(vv[i], h[3], a3);
            }
            float2 f;
            f = __half22float2(a0); accf[0] += f.x; accf[1] += f.y;
            f = __half22float2(a1); accf[2] += f.x; accf[3] += f.y;
            f = __half22float2(a2); accf[4] += f.x; accf[5] += f.y;
            f = __half22float2(a3); accf[6] += f.x; accf[7] += f.y;
        }

        if (ld) {
            float d = 0.f;
            uint4 su = make_uint4(0u, 0u, 0u, 0u);
            if (valid_n) {
                d = g_dis[n];
                su = __ldg(xw4 + (size_t)n * 12 + hl);
            }
            const __half2* sh = (const __half2*)&su;
            float4 b0 = *(const float4*)(b + hl * 8);
            float4 b1 = *(const float4*)(b + hl * 8 + 4);
            __half2 o[4];
            float2 s;
            s = __half22float2(sh[0]);
            o[0] = __floats2half2_rn(fmaxf(d * (accf[0] + s.x) + b0.x, 0.f),
                                     fmaxf(d * (accf[1] + s.y) + b0.y, 0.f));
            s = __half22float2(sh[1]);
            o[1] = __floats2half2_rn(fmaxf(d * (accf[2] + s.x) + b0.z, 0.f),
                                     fmaxf(d * (accf[3] + s.y) + b0.w, 0.f));
            s = __half22float2(sh[2]);
            o[2] = __floats2half2_rn(fmaxf(d * (accf[4] + s.x) + b1.x, 0.f),
                                     fmaxf(d * (accf[5] + s.y) + b1.y, 0.f));
            s = __half22float2(sh[3]);
            o[3] = __floats2half2_rn(fmaxf(d * (accf[6] + s.x) + b1.z, 0.f),
                                     fmaxf(d * (accf[7] + s.y) + b1.w, 0.f));
            *(uint4*)&actS[nloc * LDA + hl * 8] = *(const uint4*)o;
        }
    }
    __syncthreads();

    const int wm = wid >> 1;
    const int wn = wid & 1;
    float acc[2][NT][4];
#pragma unroll
    for (int mt = 0; mt < 2; mt++)
#pragma unroll
        for (int nt = 0; nt < NT; nt++)
#pragma unroll
            for (int q = 0; q < 4; q++) acc[mt][nt][q] = 0.0f;

#pragma unroll
    for (int ks = 0; ks < FIN / 16; ks++) {
        unsigned a[2][4];
#pragma unroll
        for (int mt = 0; mt < 2; mt++) {
            int row = wm * 32 + mt * 16 + (lane & 15);
            int col = ks * 16 + (lane >> 4) * 8;
            ldsm_x4(a[mt], smem_u32(&actS[row * LDA + col]));
        }
        unsigned bb[NT][2];
#pragma unroll
        for (int np = 0; np < NT / 2; np++) {
            int row = ks * 16 + (lane & 15);
            int col = wn * (NT * 8) + np * 16 + (lane >> 4) * 8;
            unsigned r4[4];
            ldsm_x4t(r4, smem_u32(&Bs[row * LDB + col]));
            bb[2 * np][0]     = r4[0]; bb[2 * np][1]     = r4[1];
            bb[2 * np + 1][0] = r4[2]; bb[2 * np + 1][1] = r4[3];
        }
#pragma unroll
        for (int mt = 0; mt < 2; mt++)
#pragma unroll
            for (int nt = 0; nt < NT; nt++)
                mma16816(acc[mt][nt], a[mt], bb[nt]);
    }

#pragma unroll
    for (int mt = 0; mt < 2; mt++) {
        int r_lo = rowblk + wm * 32 + mt * 16 + (lane >> 2);
        int r_hi = r_lo + 8;
        float dl = (r_lo < N) ? g_dis[r_lo] : 0.f;
        float dh = (r_hi < N) ? g_dis[r_hi] : 0.f;
#pragma unroll
        for (int nt = 0; nt < NT; nt++) {
            int c = wn * (NT * 8) + nt * 8 + (lane & 3) * 2;
            if (r_lo < N)
                *(__half2*)&xwout[(size_t)r_lo * LDOUT + c] =
                    __floats2half2_rn(dl * acc[mt][nt][0], dl * acc[mt][nt][1]);
            if (r_hi < N)
                *(__half2*)&xwout[(size_t)r_hi * LDOUT + c] =
                    __floats2half2_rn(dh * acc[mt][nt][2], dh * acc[mt][nt][3]);
        }
    }
}

// ---------------------------------------------------------------------------
// 7) Gather30 + relu + mean-pool atomics (xw3' is dis-scaled; stride 32)
// ---------------------------------------------------------------------------
__global__ __launch_bounds__(256) void gather30_kernel(
    const __half2* __restrict__ xw, const float* __restrict__ b, int N)
{
    const int lane = threadIdx.x & 31;
    const int hl = lane & 15;
    const int hh = lane >> 4;
    const int n = (((blockIdx.x * blockDim.x + threadIdx.x) >> 5) << 1) + hh;
    const bool valid_n = (n < N);

    int beg = 0, len = 0;
    if (valid_n) {
        beg = g_rowptr[n];
        len = g_rowptr[n + 1] - beg;
    }
    const int lenOther = __shfl_xor_sync(0xffffffffu, len, 16);
    const int lenMax = max(len, lenOther);
    const int last = (len > 0) ? (beg + len - 1) : 0;

    float ax = 0.f, ay = 0.f;
    const __half2 hz = __floats2half2_rn(0.f, 0.f);

    int2 cv[4];
#pragma unroll
    for (int i = 0; i < 4; i++) {
        int idx = beg + i;
        idx = (idx <= last) ? idx : last;
        cv[i] = __ldg(&g_csr[idx]);
    }

    for (int k = 0; k < lenMax; k += 4) {
        __half2 u[4], vv[4];
#pragma unroll
        for (int i = 0; i < 4; i++) {
            vv[i] = (k + i < len) ? pun_h2((unsigned)cv[i].y) : hz;
            u[i] = __ldg(xw + (size_t)cv[i].x * 16 + hl);
        }
#pragma unroll
        for (int i = 0; i < 4; i++) {
            int idx = beg + k + 4 + i;
            idx = (idx <= last) ? idx : last;
            cv[i] = __ldg(&g_csr[idx]);
        }
        __half2 a0 = hz;
#pragma unroll
        for (int i = 0; i < 4; i++) a0 = __hfma2(vv[i], u[i], a0);
        float2 f = __half22float2(a0);
        ax += f.x; ay += f.y;
    }

    if (valid_n) {
        const float d = g_dis[n];
        const int g = g_bat[n];
        if (hl < 15) {
            float2 s = __half22float2(__ldg(xw + (size_t)n * 16 + hl));
            float2 bb = *(const float2*)(b + 2 * hl);
            float v0 = fmaxf(d * (ax + s.x) + bb.x, 0.f);
            float v1 = fmaxf(d * (ay + s.y) + bb.y, 0.f);
            atomicAdd(&g_pool[g * F3 + 2 * hl],     v0);
            atomicAdd(&g_pool[g * F3 + 2 * hl + 1], v1);
        } else {
            atomicAdd(&g_cnt[g], 1.0f);
        }
    }
}

// ---------------------------------------------------------------------------
// 8) classifier + softmax; resets pool/cnt for next graph replay
// ---------------------------------------------------------------------------
__global__ void final_kernel(const float* __restrict__ Wf,
                             const float* __restrict__ bf,
                             float* __restrict__ out) {
    int g = threadIdx.x;
    if (g >= G_MAX) return;
    float cnt = fmaxf(g_cnt[g], 1.0f);
    float p[F3];
#pragma unroll
    for (int j = 0; j < F3; j++) p[j] = g_pool[g * F3 + j] / cnt;
    float lo[NCLS];
    float m = -1e30f;
#pragma unroll
    for (int k = 0; k < NCLS; k++) {
        float s = bf[k];
#pragma unroll
        for (int j = 0; j < F3; j++) s += p[j] * Wf[j * NCLS + k];
        lo[k] = s;
        m = fmaxf(m, s);
    }
    float sum = 0.0f;
#pragma unroll
    for (int k = 0; k < NCLS; k++) { lo[k] = expf(lo[k] - m); sum += lo[k]; }
    float inv = 1.0f / sum;
#pragma unroll
    for (int k = 0; k < NCLS; k++) out[g * NCLS + k] = lo[k] * inv;
#pragma unroll
    for (int j = 0; j < F3; j++) g_pool[g * F3 + j] = 0.0f;
    g_cnt[g] = 0.0f;
}

// ---------------------------------------------------------------------------
// Launch
// ---------------------------------------------------------------------------
extern "C" void kernel_launch(void* const* d_in, const int* in_sizes, int n_in,
                              void* d_out, int out_size) {
    const float* x   = (const float*)d_in[0];
    const void*  ei  = d_in[1];
    const float* ew  = (const float*)d_in[2];
    const void*  bat = d_in[3];
    const float* W1  = (const float*)d_in[4];
    const float* b1  = (const float*)d_in[5];
    const float* W2  = (const float*)d_in[6];
    const float* b2  = (const float*)d_in[7];
    const float* W3  = (const float*)d_in[8];
    const float* b3  = (const float*)d_in[9];
    const float* Wf  = (const float*)d_in[10];
    const float* bf  = (const float*)d_in[11];
    float* out = (float*)d_out;

    const int E = in_sizes[2];
    const int N = in_sizes[3];

    __half *pXW, *pXW2;
    cudaGetSymbolAddress((void**)&pXW,  g_xw);
    cudaGetSymbolAddress((void**)&pXW2, g_xw2);

    const int TB = 256;
    const int E4 = (E + 3) / 4;
    const int gPrep = (max(E4, N) + TB - 1) / TB;
    const int gPlace = (E4 + TB - 1) / TB;
    const int gGemm = (N + 127) / 128;
    const int gGather = ((N + 1) / 2 * 32 + TB - 1) / TB;
    const int gScale = (N * 12 + TB - 1) / TB;
    const int NB = (N + SCAN_BN - 1) / SCAN_BN;

    const bool fork = g_sh.ok;
    if (fork) {
        cudaEventRecord(g_sh.evFork, 0);
        cudaStreamWaitEvent(g_sh.s, g_sh.evFork, 0);
        gemm1_hmma<<<gGemm, TB, 0, g_sh.s>>>(x, W1, pXW, N);
    }

    detect_kernel<<<1, 256>>>((const unsigned*)ei);
    prep_kernel<<<gPrep, TB>>>(ei, bat, ew, E, N);
    scanA_kernel<<<NB, 256>>>(N);
    scanB_kernel<<<1, 128>>>(NB, N);
    scanC_kernel<<<NB, 256>>>(N);

    if (fork) {
        cudaEventRecord(g_sh.evFork2, 0);
        cudaStreamWaitEvent(g_sh.s, g_sh.evFork2, 0);
        xwscale_kernel<<<gScale, TB, 0, g_sh.s>>>((__half2*)pXW, N);
        cudaEventRecord(g_sh.evJoin, g_sh.s);
    }

    place_kernel<<<gPlace, TB>>>(ei, E);

    if (fork) {
        cudaStreamWaitEvent(0, g_sh.evJoin, 0);
    } else {
        gemm1_hmma<<<gGemm, TB>>>(x, W1, pXW, N);
        xwscale_kernel<<<gScale, TB>>>((__half2*)pXW, N);
    }

    fused_gg_kernel<96, 96, 96><<<gGemm, TB>>>(
        (const __half2*)pXW, b1, W2, pXW2, N);
    fused_gg_kernel<30, 32, 32><<<gGemm, TB>>>(
        (const __half2*)pXW2, b2, W3, pXW, N);

    gather30_kernel<<<gGather, TB>>>((const __half2*)pXW, b3, N);
    final_kernel<<<1, 256>>>(Wf, bf, out);

    (void)n_in; (void)out_size;
}